// round 7
// baseline (speedup 1.0000x reference)
#include <cuda_runtime.h>

// CustomLinearRNN via chunked parallel scan (R7: packed-pair SIMT GEMMs).
// h_t = A4 h_{t-1} + A3 x_t ; known_t = A1 x_t + A2 h_{t-1}
//  ksq x5 : P = A4^32
//  K1 : UZ[t] = [A3;A1] x_t   (persistent, grid 148)
//  K2 : per-chunk zero-state scan -> W_i   (grid 128, one CTA/chunk)
//  K3 : boundary scan s_{i+1} = P s_i + W_i
//  K4 : rerun chunks from s_i, fused known  (grid 128)

#define T_STEPS 4096
#define KDIM 64
#define HDIM 128
#define BDIM 128
#define CHUNK 32
#define NCHUNK 128
#define K1_GRID 148

typedef unsigned long long u64;

// stacked scratch: rows 0..127 = U = A3 x, rows 128..191 = Z = A1 x
__device__ float g_UZ[(size_t)T_STEPS * 192 * BDIM];
__device__ float g_W[(size_t)NCHUNK * HDIM * BDIM];
__device__ float g_S[(size_t)NCHUNK * HDIM * BDIM];
__device__ float g_Pa[HDIM * HDIM];
__device__ float g_Pb[HDIM * HDIM];

__device__ __forceinline__ u64 ffma2(u64 a, u64 b, u64 c) {
    u64 d; asm("fma.rn.f32x2 %0, %1, %2, %3;" : "=l"(d) : "l"(a), "l"(b), "l"(c));
    return d;
}
__device__ __forceinline__ u64 fadd2(u64 a, u64 b) {
    u64 d; asm("add.rn.f32x2 %0, %1, %2;" : "=l"(d) : "l"(a), "l"(b));
    return d;
}
__device__ __forceinline__ u64 pk2s(float v) {
    u64 u; asm("mov.b64 %0, {%1, %1};" : "=l"(u) : "f"(v)); return u;
}
__device__ __forceinline__ void upk2(float& lo, float& hi, u64 u) {
    asm("mov.b64 {%0, %1}, %2;" : "=f"(lo), "=f"(hi) : "l"(u));
}

// ---------------- Ksq: dst = src * src (128x128) ----------------
__global__ __launch_bounds__(128, 1)
void k_sq(const float* __restrict__ src, float* __restrict__ dst)
{
    __shared__ float row[HDIM];
    const int r = blockIdx.x, c = threadIdx.x;
    row[c] = src[r * HDIM + c];
    __syncthreads();
    float a0 = 0, a1 = 0, a2 = 0, a3 = 0;
    #pragma unroll 8
    for (int k = 0; k < HDIM; k += 4) {
        a0 = fmaf(row[k],     src[(k)     * HDIM + c], a0);
        a1 = fmaf(row[k + 1], src[(k + 1) * HDIM + c], a1);
        a2 = fmaf(row[k + 2], src[(k + 2) * HDIM + c], a2);
        a3 = fmaf(row[k + 3], src[(k + 3) * HDIM + c], a3);
    }
    dst[r * HDIM + c] = (a0 + a1) + (a2 + a3);
}

// ---------------- K1: UZ = [A3;A1] X, persistent ----------------
__global__ __launch_bounds__(256, 1)
void k1_ux(const float* __restrict__ x,
           const float* __restrict__ A3,
           const float* __restrict__ A1)
{
    extern __shared__ float sm[];
    float* sWt = sm;               // [kk 64][192] transposed stacked [A3;A1]
    float* sX  = sm + 64 * 192;    // [2][kk 64][128]

    const int tid = threadIdx.x;

    for (int idx = tid; idx < 192 * 64; idx += 256) {
        const int r = idx / 64, kk = idx % 64;
        sWt[kk * 192 + r] = (r < HDIM) ? A3[r * KDIM + kk]
                                       : A1[(r - HDIM) * KDIM + kk];
    }
    // preload first x tile
    {
        const float4* xg = (const float4*)(x + (size_t)blockIdx.x * KDIM * BDIM);
        float4* s0 = (float4*)sX;
        for (int idx = tid; idx < 2048; idx += 256) s0[idx] = xg[idx];
    }
    __syncthreads();

    const int ty = tid >> 4, tx = tid & 15;
    const int r0 = ty * 12, c0 = tx * 8;

    int it = 0;
    #pragma unroll 1
    for (int t = blockIdx.x; t < T_STEPS; t += K1_GRID, it ^= 1) {
        const int tn = t + K1_GRID;
        if (tn < T_STEPS) {
            const float4* xg = (const float4*)(x + (size_t)tn * KDIM * BDIM);
            float4* sn = (float4*)(sX + (it ^ 1) * 8192);
            for (int idx = tid; idx < 2048; idx += 256) sn[idx] = xg[idx];
        }
        const float* sXc = sX + it * 8192;

        u64 acc[12][4];
        #pragma unroll
        for (int m = 0; m < 12; m++)
            #pragma unroll
            for (int j = 0; j < 4; j++) acc[m][j] = 0ull;

        #pragma unroll 2
        for (int kk = 0; kk < 64; kk++) {
            const float4 w0 = *(const float4*)&sWt[kk * 192 + r0];
            const float4 w1 = *(const float4*)&sWt[kk * 192 + r0 + 4];
            const float4 w2 = *(const float4*)&sWt[kk * 192 + r0 + 8];
            const ulonglong2 xa = *(const ulonglong2*)&sXc[kk * 128 + c0];
            const ulonglong2 xb = *(const ulonglong2*)&sXc[kk * 128 + c0 + 4];
            const u64 xv[4] = {xa.x, xa.y, xb.x, xb.y};
            const float wv[12] = {w0.x, w0.y, w0.z, w0.w,
                                  w1.x, w1.y, w1.z, w1.w,
                                  w2.x, w2.y, w2.z, w2.w};
            #pragma unroll
            for (int m = 0; m < 12; m++) {
                const u64 ws = pk2s(wv[m]);
                #pragma unroll
                for (int j = 0; j < 4; j++)
                    acc[m][j] = ffma2(ws, xv[j], acc[m][j]);
            }
        }

        #pragma unroll
        for (int m = 0; m < 12; m++) {
            float* dst = &g_UZ[((size_t)t * 192 + r0 + m) * BDIM + c0];
            *(ulonglong2*)dst       = make_ulonglong2(acc[m][0], acc[m][1]);
            *((ulonglong2*)dst + 1) = make_ulonglong2(acc[m][2], acc[m][3]);
        }
        __syncthreads();
    }
}

// ---------------- K2: zero-state chunk scan -> g_W ----------------
__global__ __launch_bounds__(256, 1)
void k2_chunkzero(const float* __restrict__ A4)
{
    extern __shared__ float sm[];
    float* sA4t = sm;               // [kk 128][128 r]
    float* sH   = sm + 128 * 128;   // [2][kk 128][128 c]

    const int ic  = blockIdx.x;
    const int tid = threadIdx.x;
    const int ty = tid >> 4, tx = tid & 15;
    const int r0 = ty * 8, c0 = tx * 8;

    for (int idx = tid; idx < 128 * 128; idx += 256) {
        const int r = idx >> 7, kk = idx & 127;
        sA4t[kk * 128 + r] = A4[idx];
    }
    for (int idx = tid; idx < 128 * 128; idx += 256) sH[idx] = 0.0f;
    __syncthreads();

    #pragma unroll 1
    for (int c = 0; c < CHUNK; c++) {
        const int t = ic * CHUNK + c;
        const float* sHc = sH + (c & 1) * 16384;
        float*       sHn = sH + ((c + 1) & 1) * 16384;

        // acc initialized with u tile (h_t = u_t + A4 h_{t-1})
        u64 acc[8][4];
        #pragma unroll
        for (int m = 0; m < 8; m++) {
            const ulonglong2* up =
                (const ulonglong2*)&g_UZ[((size_t)t * 192 + r0 + m) * BDIM + c0];
            const ulonglong2 a = up[0], b = up[1];
            acc[m][0] = a.x; acc[m][1] = a.y; acc[m][2] = b.x; acc[m][3] = b.y;
        }

        #pragma unroll 2
        for (int kk = 0; kk < 128; kk++) {
            const float4 w0 = *(const float4*)&sA4t[kk * 128 + r0];
            const float4 w1 = *(const float4*)&sA4t[kk * 128 + r0 + 4];
            const ulonglong2 ha = *(const ulonglong2*)&sHc[kk * 128 + c0];
            const ulonglong2 hb = *(const ulonglong2*)&sHc[kk * 128 + c0 + 4];
            const u64 hv[4] = {ha.x, ha.y, hb.x, hb.y};
            const float wv[8] = {w0.x, w0.y, w0.z, w0.w, w1.x, w1.y, w1.z, w1.w};
            #pragma unroll
            for (int m = 0; m < 8; m++) {
                const u64 ws = pk2s(wv[m]);
                #pragma unroll
                for (int j = 0; j < 4; j++)
                    acc[m][j] = ffma2(ws, hv[j], acc[m][j]);
            }
        }

        if (c == CHUNK - 1) {
            #pragma unroll
            for (int m = 0; m < 8; m++) {
                float* dst = &g_W[((size_t)ic * HDIM + r0 + m) * BDIM + c0];
                *(ulonglong2*)dst       = make_ulonglong2(acc[m][0], acc[m][1]);
                *((ulonglong2*)dst + 1) = make_ulonglong2(acc[m][2], acc[m][3]);
            }
        } else {
            #pragma unroll
            for (int m = 0; m < 8; m++) {
                float* dst = &sHn[(r0 + m) * 128 + c0];
                *(ulonglong2*)dst       = make_ulonglong2(acc[m][0], acc[m][1]);
                *((ulonglong2*)dst + 1) = make_ulonglong2(acc[m][2], acc[m][3]);
            }
        }
        __syncthreads();
    }
}

// ---------------- K3: boundary scan, one CTA per b ----------------
__global__ __launch_bounds__(128, 1)
void k3_scan(const float* __restrict__ h0)
{
    extern __shared__ float sm[];
    float* sP = sm;                 // [r][130] padded
    float* sS = sm + 128 * 130;

    const int b = blockIdx.x;
    const int tid = threadIdx.x;

    for (int idx = tid; idx < 128 * 128; idx += 128) {
        const int r = idx >> 7, kk = idx & 127;
        sP[r * 130 + kk] = g_Pa[idx];
    }
    float s = h0[tid * BDIM + b];
    sS[tid] = s;
    __syncthreads();

    #pragma unroll 1
    for (int i = 0; i < NCHUNK; i++) {
        g_S[((size_t)i * HDIM + tid) * BDIM + b] = s;
        const float w = g_W[((size_t)i * HDIM + tid) * BDIM + b];
        const u64* s2 = (const u64*)sS;
        const u64* p2 = (const u64*)&sP[tid * 130];
        u64 a0 = 0ull, a1 = 0ull, a2 = 0ull, a3 = 0ull;
        #pragma unroll 4
        for (int m = 0; m < 64; m += 4) {
            a0 = ffma2(p2[m],     s2[m],     a0);
            a1 = ffma2(p2[m + 1], s2[m + 1], a1);
            a2 = ffma2(p2[m + 2], s2[m + 2], a2);
            a3 = ffma2(p2[m + 3], s2[m + 3], a3);
        }
        const u64 aa = fadd2(fadd2(a0, a1), fadd2(a2, a3));
        float lo, hi; upk2(lo, hi, aa);
        s = lo + hi + w;
        __syncthreads();
        sS[tid] = s;
        __syncthreads();
    }
}

// ---------------- K4: rerun chunks + fused known ----------------
__global__ __launch_bounds__(256, 1)
void k4_final(const float* __restrict__ A4,
              const float* __restrict__ A2,
              float* __restrict__ out_known,
              float* __restrict__ out_hidden)
{
    extern __shared__ float sm[];
    float* sWt = sm;                // [kk 128][192]: r<128 A4t, r>=128 A2t
    float* sH  = sm + 128 * 192;    // [2][kk 128][128 c]

    const int ic  = blockIdx.x;
    const int tid = threadIdx.x;
    const int ty = tid >> 4, tx = tid & 15;
    const int hr0 = ty * 8;   // h rows
    const int kr0 = ty * 4;   // known rows
    const int c0  = tx * 8;

    for (int idx = tid; idx < 192 * 128; idx += 256) {
        const int r = idx >> 7, kk = idx & 127;
        sWt[kk * 192 + r] = (r < HDIM) ? A4[r * HDIM + kk]
                                       : A2[(r - HDIM) * HDIM + kk];
    }
    {
        const float4* sg = (const float4*)&g_S[(size_t)ic * HDIM * BDIM];
        float4* sh = (float4*)sH;
        for (int idx = tid; idx < 4096; idx += 256) sh[idx] = sg[idx];
    }
    __syncthreads();

    #pragma unroll 1
    for (int c = 0; c < CHUNK; c++) {
        const int t = ic * CHUNK + c;
        const float* sHc = sH + (c & 1) * 16384;
        float*       sHn = sH + ((c + 1) & 1) * 16384;

        // acch init = u tile, acck init = z tile
        u64 acch[8][4], acck[4][4];
        #pragma unroll
        for (int m = 0; m < 8; m++) {
            const ulonglong2* up =
                (const ulonglong2*)&g_UZ[((size_t)t * 192 + hr0 + m) * BDIM + c0];
            const ulonglong2 a = up[0], b = up[1];
            acch[m][0] = a.x; acch[m][1] = a.y; acch[m][2] = b.x; acch[m][3] = b.y;
        }
        #pragma unroll
        for (int m = 0; m < 4; m++) {
            const ulonglong2* zp =
                (const ulonglong2*)&g_UZ[((size_t)t * 192 + 128 + kr0 + m) * BDIM + c0];
            const ulonglong2 a = zp[0], b = zp[1];
            acck[m][0] = a.x; acck[m][1] = a.y; acck[m][2] = b.x; acck[m][3] = b.y;
        }

        #pragma unroll 2
        for (int kk = 0; kk < 128; kk++) {
            const float4 w0 = *(const float4*)&sWt[kk * 192 + hr0];
            const float4 w1 = *(const float4*)&sWt[kk * 192 + hr0 + 4];
            const float4 wk = *(const float4*)&sWt[kk * 192 + 128 + kr0];
            const ulonglong2 ha = *(const ulonglong2*)&sHc[kk * 128 + c0];
            const ulonglong2 hb = *(const ulonglong2*)&sHc[kk * 128 + c0 + 4];
            const u64 hv[4] = {ha.x, ha.y, hb.x, hb.y};
            const float wh[8] = {w0.x, w0.y, w0.z, w0.w, w1.x, w1.y, w1.z, w1.w};
            const float wz[4] = {wk.x, wk.y, wk.z, wk.w};
            #pragma unroll
            for (int m = 0; m < 8; m++) {
                const u64 ws = pk2s(wh[m]);
                #pragma unroll
                for (int j = 0; j < 4; j++)
                    acch[m][j] = ffma2(ws, hv[j], acch[m][j]);
            }
            #pragma unroll
            for (int m = 0; m < 4; m++) {
                const u64 ws = pk2s(wz[m]);
                #pragma unroll
                for (int j = 0; j < 4; j++)
                    acck[m][j] = ffma2(ws, hv[j], acck[m][j]);
            }
        }

        // known_t
        #pragma unroll
        for (int m = 0; m < 4; m++) {
            float* dst = &out_known[((size_t)t * KDIM + kr0 + m) * BDIM + c0];
            *(ulonglong2*)dst       = make_ulonglong2(acck[m][0], acck[m][1]);
            *((ulonglong2*)dst + 1) = make_ulonglong2(acck[m][2], acck[m][3]);
        }
        // h_t -> out_hidden + next smem buffer
        #pragma unroll
        for (int m = 0; m < 8; m++) {
            float* dst = &out_hidden[((size_t)t * HDIM + hr0 + m) * BDIM + c0];
            const ulonglong2 v0 = make_ulonglong2(acch[m][0], acch[m][1]);
            const ulonglong2 v1 = make_ulonglong2(acch[m][2], acch[m][3]);
            *(ulonglong2*)dst       = v0;
            *((ulonglong2*)dst + 1) = v1;
            if (c < CHUNK - 1) {
                float* sdst = &sHn[(hr0 + m) * 128 + c0];
                *(ulonglong2*)sdst       = v0;
                *((ulonglong2*)sdst + 1) = v1;
            }
        }
        __syncthreads();
    }
}

// ---------------- host ----------------
extern "C" void kernel_launch(void* const* d_in, const int* in_sizes, int n_in,
                              void* d_out, int out_size)
{
    const float* x  = (const float*)d_in[0];
    const float* h0 = (const float*)d_in[1];
    const float* A1 = (const float*)d_in[2];
    const float* A2 = (const float*)d_in[3];
    const float* A3 = (const float*)d_in[4];
    const float* A4 = (const float*)d_in[5];

    float* out_known  = (float*)d_out;
    float* out_hidden = (float*)d_out + (size_t)T_STEPS * KDIM * BDIM;

    const int smem1 = (64 * 192 + 2 * 64 * 128) * 4;        // 114688
    const int smem2 = (128 * 128 + 2 * 128 * 128) * 4;      // 196608
    const int smem3 = (128 * 130 + 128) * 4;                // 67072
    const int smem4 = (128 * 192 + 2 * 128 * 128) * 4;      // 229376

    cudaFuncSetAttribute(k1_ux,        cudaFuncAttributeMaxDynamicSharedMemorySize, smem1);
    cudaFuncSetAttribute(k2_chunkzero, cudaFuncAttributeMaxDynamicSharedMemorySize, smem2);
    cudaFuncSetAttribute(k3_scan,      cudaFuncAttributeMaxDynamicSharedMemorySize, smem3);
    cudaFuncSetAttribute(k4_final,     cudaFuncAttributeMaxDynamicSharedMemorySize, smem4);

    float *pa, *pb;
    cudaGetSymbolAddress((void**)&pa, g_Pa);
    cudaGetSymbolAddress((void**)&pb, g_Pb);

    // ksq first so ncu -s 5 lands on k1 (launch #6)
    k_sq<<<HDIM, HDIM>>>(A4, pa);   // A4^2
    k_sq<<<HDIM, HDIM>>>(pa, pb);   // A4^4
    k_sq<<<HDIM, HDIM>>>(pb, pa);   // A4^8
    k_sq<<<HDIM, HDIM>>>(pa, pb);   // A4^16
    k_sq<<<HDIM, HDIM>>>(pb, pa);   // A4^32 -> g_Pa

    k1_ux<<<K1_GRID, 256, smem1>>>(x, A3, A1);
    k2_chunkzero<<<NCHUNK, 256, smem2>>>(A4);
    k3_scan<<<BDIM, 128, smem3>>>(h0);
    k4_final<<<NCHUNK, 256, smem4>>>(A4, A2, out_known, out_hidden);

    (void)in_sizes; (void)n_in; (void)out_size;
}